// round 11
// baseline (speedup 1.0000x reference)
#include <cuda_runtime.h>
#include <cstdint>
#include <cstddef>

// Problem dims (fixed)
#define BB   32
#define TT   4096
#define DIN  256
#define HH   256
#define G4   1024   // 4*H

// ---------------- scratch (static device arrays; no allocation) ----------------
__device__ float g_xg[(size_t)BB * TT * G4];   // 512 MB : x @ Wx + b
__device__ float g_hseq[(size_t)BB * TT * HH]; // 128 MB : h_t for all t
// tagged exchange: [slot][group][hidx][batch] = {h, tag} in one 8B word,
// accessed ONLY with relaxed atomics (spec-guaranteed single-copy atomic).
__device__ unsigned long long g_hx[2][16][256][2];

__global__ void init_kernel() {   // zero tags for graph replays
    const int i = blockIdx.x * 256 + threadIdx.x;   // 16384 u64s
    ((unsigned long long*)g_hx)[i] = 0ull;
}

// ---------------- PTX helpers ----------------
__device__ __forceinline__ unsigned long long ffma2(unsigned long long a,
                                                    unsigned long long b,
                                                    unsigned long long c) {
    unsigned long long d;
    asm("fma.rn.f32x2 %0, %1, %2, %3;" : "=l"(d) : "l"(a), "l"(b), "l"(c));
    return d;
}
__device__ __forceinline__ unsigned long long addx2(unsigned long long a,
                                                    unsigned long long b) {
    unsigned long long d;
    asm("add.rn.f32x2 %0, %1, %2;" : "=l"(d) : "l"(a), "l"(b));
    return d;
}
__device__ __forceinline__ unsigned long long pk2(float lo, float hi) {
    unsigned long long r;
    asm("mov.b64 %0, {%1,%2};" : "=l"(r) : "f"(lo), "f"(hi));
    return r;
}
__device__ __forceinline__ float2 unpk2(unsigned long long v) {
    float lo, hi;
    asm("mov.b64 {%0,%1}, %2;" : "=f"(lo), "=f"(hi) : "l"(v));
    return make_float2(lo, hi);
}
// relaxed 8B atomics: tear-free by the PTX memory model, no fence cost
__device__ __forceinline__ void st_rlx64(unsigned long long* p, unsigned long long v) {
    asm volatile("st.relaxed.gpu.global.u64 [%0], %1;" :: "l"(p), "l"(v) : "memory");
}
__device__ __forceinline__ unsigned long long ld_rlx64(const unsigned long long* p) {
    unsigned long long v;
    asm volatile("ld.relaxed.gpu.global.u64 %0, [%1];" : "=l"(v) : "l"(p) : "memory");
    return v;
}

// ---------------- fp32 GEMM (f32x2 inner loop): C = A@B + bias ----------------
__global__ void __launch_bounds__(256) sgemm_bias_128(
    const float* __restrict__ A, const float* __restrict__ B,
    const float* __restrict__ bias, float* __restrict__ C,
    int M, int N, int K)
{
    __shared__ __align__(16) float As[8][128];
    __shared__ __align__(16) float Bs[8][128];

    const int tid = threadIdx.x;
    const int bm  = blockIdx.y;
    const int bn  = blockIdx.x;
    const int tx  = tid & 15;
    const int ty  = tid >> 4;

    const int arow = tid >> 1;
    const int ak   = (tid & 1) * 4;
    const int brow = tid >> 5;
    const int bcol = (tid & 31) * 4;

    const float* Aptr = A + (size_t)(bm * 128 + arow) * K + ak;
    const float* Bptr = B + (size_t)brow * N + bn * 128 + bcol;

    unsigned long long acc2[8][4];
#pragma unroll
    for (int i = 0; i < 8; i++)
#pragma unroll
        for (int jp = 0; jp < 4; jp++) acc2[i][jp] = 0ull;

    for (int k0 = 0; k0 < K; k0 += 8) {
        const float4 va = *(const float4*)(Aptr + k0);
        const float4 vb = *(const float4*)(Bptr + (size_t)k0 * N);
        __syncthreads();
        As[ak + 0][arow] = va.x;
        As[ak + 1][arow] = va.y;
        As[ak + 2][arow] = va.z;
        As[ak + 3][arow] = va.w;
        *(float4*)&Bs[brow][bcol] = vb;
        __syncthreads();

#pragma unroll
        for (int k = 0; k < 8; k++) {
            float a0[4], a1[4];
            *(float4*)a0 = *(const float4*)&As[k][ty * 4];
            *(float4*)a1 = *(const float4*)&As[k][64 + ty * 4];
            const ulonglong2 bp0 = *(const ulonglong2*)&Bs[k][tx * 4];
            const ulonglong2 bp1 = *(const ulonglong2*)&Bs[k][64 + tx * 4];
#pragma unroll
            for (int i = 0; i < 4; i++) {
                const unsigned long long ad0 = pk2(a0[i], a0[i]);
                acc2[i][0] = ffma2(ad0, bp0.x, acc2[i][0]);
                acc2[i][1] = ffma2(ad0, bp0.y, acc2[i][1]);
                acc2[i][2] = ffma2(ad0, bp1.x, acc2[i][2]);
                acc2[i][3] = ffma2(ad0, bp1.y, acc2[i][3]);
                const unsigned long long ad1 = pk2(a1[i], a1[i]);
                acc2[i + 4][0] = ffma2(ad1, bp0.x, acc2[i + 4][0]);
                acc2[i + 4][1] = ffma2(ad1, bp0.y, acc2[i + 4][1]);
                acc2[i + 4][2] = ffma2(ad1, bp1.x, acc2[i + 4][2]);
                acc2[i + 4][3] = ffma2(ad1, bp1.y, acc2[i + 4][3]);
            }
        }
    }

    const float* bptr = bias + bn * 128;
    const ulonglong2 bv0 = *(const ulonglong2*)&bptr[tx * 4];
    const ulonglong2 bv1 = *(const ulonglong2*)&bptr[64 + tx * 4];

#pragma unroll
    for (int i = 0; i < 8; i++) {
        const int row = bm * 128 + ((i < 4) ? (ty * 4 + i) : (64 + ty * 4 + (i - 4)));
        ulonglong2 o0, o1;
        o0.x = addx2(acc2[i][0], bv0.x);
        o0.y = addx2(acc2[i][1], bv0.y);
        o1.x = addx2(acc2[i][2], bv1.x);
        o1.y = addx2(acc2[i][3], bv1.y);
        *(ulonglong2*)&C[(size_t)row * N + bn * 128 + tx * 4]      = o0;
        *(ulonglong2*)&C[(size_t)row * N + bn * 128 + 64 + tx * 4] = o1;
    }
}

// ---------------- recurrence: K-packed outer product, no shfl/pack ------------
// 128 CTAs = 16 groups (batch pairs) x 8 ranks. Rank j owns 128 gate-columns:
// local col c -> global colg = (c>>5)*256 + j*32 + (c&31)  (gate = c>>5).
// Warp w: K-slice [64*(w&3), +64), column half (w>>2)*64. Lane owns 2 adjacent
// cols c0 = 64*(w>>2) + 2*lane (same gate; colg adjacent). Weights packed along
// K: w2[k2][cc] = (Wh[2k2][cg], Wh[2k2+1][cg]) -- 64 b64 = 128 regs.
// h is read as naturally-packed b64 pairs from SMEM at a warp-uniform address
// (broadcast LDS, 1 wavefront): NO shfl, NO pack MOVs in the loop.
// 128 FFMA2/lane/step = 512-cyc issue floor; even/odd accumulator split.
// Reduce: STS red[4][2][128] (float2) -> 1 barrier -> 64 act threads sum the
// 4 K-slices per gate directly (16 LDS), LSTM math (csm SMEM), tagged store.
// Exchange: R7 relaxed-atomic {h, tag} words; all 256 threads poll their own
// two words, write hs, 1 barrier. 2 barriers/step total.
__global__ void __launch_bounds__(256, 1) lstm_rec(const float* __restrict__ Wh)
{
    const int cta  = blockIdx.x;
    const int grp  = cta >> 3;
    const int j    = cta & 7;
    const int b0   = grp * 2, b1 = b0 + 1;
    const int tid  = threadIdx.x;
    const int w    = tid >> 5;
    const int lane = tid & 31;
    const int wk   = w & 3;        // K-slice index
    const int wc   = w >> 2;       // column half

    __shared__ __align__(16) float hs[2][256];        // batch x h
    __shared__ __align__(16) float red[4][2][128];    // k-slice x batch x col
    __shared__ float csm[2][32];

    // persistent K-packed weights for this lane's 2 columns
    const int c0  = 64 * wc + 2 * lane;                       // local col (even)
    const int cg0 = (c0 >> 5) * 256 + j * 32 + (c0 & 31);     // global col; cg0+1 adjacent
    unsigned long long w2[32][2];
    {
#pragma unroll
        for (int k2 = 0; k2 < 32; k2++) {
            const float* r0 = Wh + (size_t)(64 * wk + 2 * k2) * G4;
            const float* r1 = r0 + G4;
            w2[k2][0] = pk2(__ldg(&r0[cg0]),     __ldg(&r1[cg0]));
            w2[k2][1] = pk2(__ldg(&r0[cg0 + 1]), __ldg(&r1[cg0 + 1]));
        }
    }

    hs[0][tid] = 0.f;
    hs[1][tid] = 0.f;
    if (tid < 64) csm[tid >> 5][tid & 31] = 0.f;
    __syncthreads();

    // activation-thread mapping + xg prefetch for t=0
    const int bb = tid >> 5;        // batch (valid for tid<64)
    const int ll = tid & 31;        // h-offset within rank's 32
    float xq0 = 0.f, xq1 = 0.f, xq2 = 0.f, xq3 = 0.f;
    if (tid < 64) {
        const float* xp = g_xg + ((size_t)((b0 + bb) * TT)) * G4 + j * 32 + ll;
        xq0 = __ldg(xp);
        xq1 = __ldg(xp + 256);
        xq2 = __ldg(xp + 512);
        xq3 = __ldg(xp + 768);
    }

    for (int t = 0; t < TT; t++) {
        // ---- K-packed partial GEMV over this warp's K-slice ----
        const unsigned long long* hp0 = (const unsigned long long*)&hs[0][64 * wk];
        const unsigned long long* hp1 = (const unsigned long long*)&hs[1][64 * wk];
        unsigned long long a0b0[2] = {0ull, 0ull}, a1b0[2] = {0ull, 0ull};
        unsigned long long a0b1[2] = {0ull, 0ull}, a1b1[2] = {0ull, 0ull};
#pragma unroll
        for (int k2 = 0; k2 < 32; k2++) {
            const unsigned long long h0 = hp0[k2];   // broadcast LDS.64
            const unsigned long long h1 = hp1[k2];
            const int par = k2 & 1;
            a0b0[par] = ffma2(w2[k2][0], h0, a0b0[par]);
            a1b0[par] = ffma2(w2[k2][1], h0, a1b0[par]);
            a0b1[par] = ffma2(w2[k2][0], h1, a0b1[par]);
            a1b1[par] = ffma2(w2[k2][1], h1, a1b1[par]);
        }
        {
            const float2 u0 = unpk2(addx2(a0b0[0], a0b0[1]));   // col c0,   batch0
            const float2 u1 = unpk2(addx2(a1b0[0], a1b0[1]));   // col c0+1, batch0
            const float2 v0 = unpk2(addx2(a0b1[0], a0b1[1]));   // col c0,   batch1
            const float2 v1 = unpk2(addx2(a1b1[0], a1b1[1]));   // col c0+1, batch1
            *(float2*)&red[wk][0][c0] = make_float2(u0.x + u0.y, u1.x + u1.y);
            *(float2*)&red[wk][1][c0] = make_float2(v0.x + v0.y, v1.x + v1.y);
        }
        __syncthreads();   // red ready; also: all reads of hs done

        const int   sl   = (t + 1) & 1;
        const float tagf = (float)(t + 1);

        // ---- activation: 64 threads = 2 batches x 32 h; gates reduced inline ----
        if (tid < 64) {
            const float gi = xq0 + red[0][bb][ll]      + red[1][bb][ll]
                                 + red[2][bb][ll]      + red[3][bb][ll];
            const float gf = xq1 + red[0][bb][32 + ll] + red[1][bb][32 + ll]
                                 + red[2][bb][32 + ll] + red[3][bb][32 + ll];
            const float gg = xq2 + red[0][bb][64 + ll] + red[1][bb][64 + ll]
                                 + red[2][bb][64 + ll] + red[3][bb][64 + ll];
            const float go = xq3 + red[0][bb][96 + ll] + red[1][bb][96 + ll]
                                 + red[2][bb][96 + ll] + red[3][bb][96 + ll];
            const float cprev = csm[bb][ll];
            const float si = 1.f / (1.f + __expf(-gi));
            const float sf = 1.f / (1.f + __expf(-gf));
            const float so = 1.f / (1.f + __expf(-go));
            const float tg = 2.f / (1.f + __expf(-2.f * gg)) - 1.f;
            const float cn = sf * cprev + si * tg;
            const float tc = 2.f / (1.f + __expf(-2.f * cn)) - 1.f;
            const float hn = so * tc;
            csm[bb][ll] = cn;
            const int hidx = j * 32 + ll;
            if (t + 1 < TT)
                st_rlx64(&g_hx[sl][grp][hidx][bb], pk2(hn, tagf));
            g_hseq[((size_t)((b0 + bb) * TT + t)) * HH + hidx] = hn;
        }
        // NO barrier: warps 2-7 go straight to polling while warps 0-1 finish

        if (t + 1 < TT) {
            // prefetch next xg (in flight during the poll)
            if (tid < 64) {
                const float* xp = g_xg + ((size_t)((b0 + bb) * TT + (t + 1))) * G4
                                + j * 32 + ll;
                xq0 = __ldg(xp);
                xq1 = __ldg(xp + 256);
                xq2 = __ldg(xp + 512);
                xq3 = __ldg(xp + 768);
            }
            // each thread polls its OWN two tagged words; hit == data
            const unsigned long long* src = &g_hx[sl][grp][tid][0];
            float2 d0, d1;
            for (;;) {
                const unsigned long long v0 = ld_rlx64(src);
                const unsigned long long v1 = ld_rlx64(src + 1);
                d0 = unpk2(v0);
                d1 = unpk2(v1);
                if (d0.y >= tagf && d1.y >= tagf) break;
            }
            hs[0][tid] = d0.x;
            hs[1][tid] = d1.x;
            __syncthreads();
        }
    }
}

// ---------------- launch ----------------
extern "C" void kernel_launch(void* const* d_in, const int* in_sizes, int n_in,
                              void* d_out, int out_size)
{
    const float* x  = (const float*)d_in[0];   // [B,T,DIN]
    const float* Wx = (const float*)d_in[1];   // [DIN,4H]
    const float* Wh = (const float*)d_in[2];   // [H,4H]
    const float* b  = (const float*)d_in[3];   // [4H]
    const float* Wo = (const float*)d_in[4];   // [H,DOUT]
    const float* bo = (const float*)d_in[5];   // [DOUT]
    float* out = (float*)d_out;                // [B,T,DOUT]

    float *xg_ptr = nullptr, *hseq_ptr = nullptr;
    cudaGetSymbolAddress((void**)&xg_ptr, g_xg);
    cudaGetSymbolAddress((void**)&hseq_ptr, g_hseq);

    // reset exchange tags (graph replays reuse device state)
    init_kernel<<<64, 256>>>();

    // 1) xg = x @ Wx + b : [131072,256] @ [256,1024]
    {
        dim3 grid(G4 / 128, (BB * TT) / 128);   // (8, 1024)
        sgemm_bias_128<<<grid, 256>>>(x, Wx, b, xg_ptr, BB * TT, G4, DIN);
    }

    // 2) recurrence over 4096 steps (16 groups x 8 CTAs, all co-resident)
    lstm_rec<<<128, 256>>>(Wh);

    // 3) out = hseq @ Wo + bo : [131072,256] @ [256,256]
    {
        dim3 grid(256 / 128, (BB * TT) / 128);  // (2, 1024)
        sgemm_bias_128<<<grid, 256>>>(hseq_ptr, Wo, bo, out, BB * TT, 256, HH);
    }
}